// round 7
// baseline (speedup 1.0000x reference)
#include <cuda_runtime.h>
#include <cstdint>
#include <cstddef>

// ---------------------------------------------------------------------------
// 2-layer LSTM, B=32, T=512, I=H=1024, fp32 — wavefront-pipelined layers.
//
// CTAs 0..63   = group A: layer 0 at time t=s      (active s < 512)
// CTAs 64..127 = group B: layer 1 at time t=s-1    (active s >= 1)
// 513 wavefront steps, one grid barrier each. Per step each CTA does
// 64 gate-rows x 32 batches x k=2048:
//   - 16 k-stages of 128, cp.async 4-deep pipeline, ONE __syncthreads/stage
//   - 16 warps (512 thr): 4-way k-split x 4 row-blocks; thread tile
//     4 rows x 4 batches -> 32 FFMA2 per 8 LDS.128, conflict-free swizzles
//   - weights pre-rearranged once into per-(cta,stage) contiguous swizzled
//     blocks; c-state in registers for all 512 steps
// ---------------------------------------------------------------------------

#define NCTA   128
#define NTHR   512
#define TSTEPS 512
#define HDIM   1024

#define OFF_W   0u         // 4 x 32KB weight stage buffers
#define OFF_C   131072u    // 4 x 16KB comb stage buffers
#define OFF_GS  196608u    // gs4[4][64][33] partial gate sums
#define SMEM_BYTES (196608 + 4 * 64 * 33 * 4)   // 230400

// rearranged weights: [l][cta64][stage16][2048 float4] (row/kq swizzled)
__device__ __align__(16) float g_Wre[2u * 64u * 16u * 2048u * 4u];
// h ping-pong: [layer][pp][b*1024+n]
__device__ __align__(16) float g_h[2 * 2 * 32 * HDIM];
__device__ unsigned g_bar_count;
__device__ volatile unsigned g_bar_gen;

union F2 { unsigned long long u; float2 f; };

__device__ __forceinline__ void ffma2(unsigned long long& acc,
                                      unsigned long long a,
                                      unsigned long long b) {
    asm volatile("fma.rn.f32x2 %0, %1, %2, %0;" : "+l"(acc) : "l"(a), "l"(b));
}
__device__ __forceinline__ void cpa16(uint32_t dst, const void* src) {
    asm volatile("cp.async.cg.shared.global [%0], [%1], 16;" :: "r"(dst), "l"(src));
}
__device__ __forceinline__ void cp_commit() {
    asm volatile("cp.async.commit_group;");
}
template<int N> __device__ __forceinline__ void cp_wait() {
    asm volatile("cp.async.wait_group %0;" :: "n"(N));
}

__device__ __forceinline__ void grid_bar() {
    __syncthreads();
    if (threadIdx.x == 0) {
        __threadfence();
        unsigned gen = g_bar_gen;
        if (atomicAdd(&g_bar_count, 1u) == NCTA - 1) {
            g_bar_count = 0;
            __threadfence();
            g_bar_gen = gen + 1;
        } else {
            while (g_bar_gen == gen) { __nanosleep(32); }
        }
        __threadfence();
    }
    __syncthreads();
}

// stage weights: contiguous pre-swizzled 32KB block -> smem buffer
__device__ __forceinline__ void fetch_W(uint32_t sb, uint32_t dstoff,
                                        int l, int gcta, int s, int tid) {
    const float4* src = ((const float4*)g_Wre) +
                        (((size_t)l * 64 + gcta) * 16 + s) * 2048;
    uint32_t d = sb + OFF_W + dstoff;
    #pragma unroll
    for (int i = 0; i < 4; i++) {
        int m = tid + i * 512;
        cpa16(d + m * 16, src + m);
    }
}

// stage activations: 32 b x 128 k, swizzled slot c holds kq = c ^ (b>>2)
__device__ __forceinline__ void fetch_C(uint32_t sb, uint32_t dstoff,
                                        const float* base, size_t stride,
                                        int tid) {
    uint32_t d = sb + OFF_C + dstoff;
    #pragma unroll
    for (int i = 0; i < 2; i++) {
        int m = tid + i * 512;
        int b = m >> 5, c = m & 31;
        cpa16(d + m * 16,
              base + (size_t)b * stride + ((c ^ (b >> 2)) << 2));
    }
}

// one-time weight rearrangement
extern "C" __global__ void lstm_rearrange(const float* __restrict__ W0,
                                          const float* __restrict__ W1) {
    unsigned gid = blockIdx.x * 256u + threadIdx.x;
    #pragma unroll
    for (int i = 0; i < 4; i++) {
        unsigned m   = gid + (unsigned)i * 1048576u;
        unsigned c   = m & 31u;
        unsigned r   = (m >> 5) & 63u;
        unsigned s   = (m >> 11) & 15u;
        unsigned cta = (m >> 15) & 63u;
        unsigned l   = m >> 21;
        unsigned sw  = ((r >> 2) & 3u) * 2u;
        unsigned gr  = (r >> 4) * 1024u + cta * 16u + (r & 15u);
        const float* W = l ? W1 : W0;
        ((float4*)g_Wre)[m] =
            ((const float4*)W)[(size_t)gr * 512 + s * 32 + (c ^ sw)];
    }
}

extern "C" __global__ void __launch_bounds__(NTHR, 1)
lstm_persist(const float* __restrict__ x,
             const float* __restrict__ b0,
             const float* __restrict__ b1,
             float* __restrict__ out)
{
    extern __shared__ char sm[];
    const uint32_t sb = (uint32_t)__cvta_generic_to_shared(sm);
    float* gs4 = (float*)(sm + OFF_GS);      // [4][64][33]

    const int tid    = threadIdx.x;
    const int cta    = blockIdx.x;
    const int gsel   = cta >> 6;        // 0 = layer0 (A), 1 = layer1 (B)
    const int gcta   = cta & 63;
    const int w      = tid >> 5;        // 0..15
    const int lane   = tid & 31;
    const int ksplit = w >> 2;          // 0..3: kq-quarter within stage
    const int rblk   = w & 3;           // 4 row-blocks of 16 rows
    const int rlane  = lane >> 3;       // 0..3
    const int blane  = lane & 7;        // 0..7
    const int rbase  = rblk * 16 + rlane * 4;  // first of thread's 4 rows
    const int wsw    = rlane * 2;       // W kq swizzle for this thread

    // pointwise: 1 item per thread: (neuron nj, batch pb)
    const int nj = tid & 15, pb = tid >> 4;

    // zero h state
    {
        int base = cta * 1024 + tid;
        #pragma unroll
        for (int k = 0; k < 2; k++) g_h[base + k * 512] = 0.f;
    }

    const float* bias = gsel ? b1 : b0;
    float br[4];
    #pragma unroll
    for (int g = 0; g < 4; ++g)
        br[g] = bias[g * HDIM + gcta * 16 + nj];
    float cst = 0.f;

    grid_bar();

    #pragma unroll 1
    for (int s = 0; s <= TSTEPS; ++s) {
        const bool active = gsel ? (s >= 1) : (s < TSTEPS);
        const int  t      = gsel ? (s - 1) : s;          // my time index
        const int  pprev  = (s + 1) & 1;                 // h0(s-1) parity

        if (active) {
            // ---- stage source resolver ----
            auto src_of = [&](int st, const float*& base, size_t& stride) {
                if (gsel == 0) {
                    if (st < 8) { base = x + (size_t)t * 1024 + st * 128; stride = 524288; }
                    else        { base = g_h + pprev * 32768 + (st - 8) * 128; stride = 1024; }
                } else {
                    if (st < 8) { base = g_h + pprev * 32768 + st * 128; stride = 1024; }
                    else        { base = g_h + (2 + (s & 1)) * 32768 + (st - 8) * 128; stride = 1024; }
                }
            };

            // ---- bootstrap pipeline: stages 0,1 ----
            {
                const float* cb; size_t cs;
                fetch_W(sb, 0u, gsel, gcta, 0, tid);
                src_of(0, cb, cs); fetch_C(sb, 0u, cb, cs, tid);
                cp_commit();
                fetch_W(sb, 32768u, gsel, gcta, 1, tid);
                src_of(1, cb, cs); fetch_C(sb, 16384u, cb, cs, tid);
                cp_commit();
            }

            unsigned long long acc[32];
            #pragma unroll
            for (int i = 0; i < 32; i++) acc[i] = 0ull;

            #pragma unroll 1
            for (int st = 0; st < 16; ++st) {
                if (st + 2 < 16) {
                    const int nf = st + 2;
                    fetch_W(sb, (uint32_t)((nf & 3) << 15), gsel, gcta, nf, tid);
                    const float* cb; size_t cs;
                    src_of(nf, cb, cs);
                    fetch_C(sb, (uint32_t)((nf & 3) << 14), cb, cs, tid);
                }
                cp_commit();
                cp_wait<2>();
                __syncthreads();

                const char* Wp = sm + ((st & 3) << 15) + rbase * 512;
                const char* Cp = sm + OFF_C + ((st & 3) << 14) + blane * 2048;
                const int kq0 = ksplit * 8;
                #pragma unroll 4
                for (int kq = kq0; kq < kq0 + 8; ++kq) {
                    const int wo = (kq ^ wsw)   << 4;
                    const int co = (kq ^ blane) << 4;
                    ulonglong2 wv0 = *(const ulonglong2*)(Wp + wo);
                    ulonglong2 wv1 = *(const ulonglong2*)(Wp + wo + 512);
                    ulonglong2 wv2 = *(const ulonglong2*)(Wp + wo + 1024);
                    ulonglong2 wv3 = *(const ulonglong2*)(Wp + wo + 1536);
                    ulonglong2 cv0 = *(const ulonglong2*)(Cp + co);
                    ulonglong2 cv1 = *(const ulonglong2*)(Cp + co + 512);
                    ulonglong2 cv2 = *(const ulonglong2*)(Cp + co + 1024);
                    ulonglong2 cv3 = *(const ulonglong2*)(Cp + co + 1536);
                    ffma2(acc[0],  wv0.x, cv0.x); ffma2(acc[1],  wv0.y, cv0.y);
                    ffma2(acc[2],  wv0.x, cv1.x); ffma2(acc[3],  wv0.y, cv1.y);
                    ffma2(acc[4],  wv0.x, cv2.x); ffma2(acc[5],  wv0.y, cv2.y);
                    ffma2(acc[6],  wv0.x, cv3.x); ffma2(acc[7],  wv0.y, cv3.y);
                    ffma2(acc[8],  wv1.x, cv0.x); ffma2(acc[9],  wv1.y, cv0.y);
                    ffma2(acc[10], wv1.x, cv1.x); ffma2(acc[11], wv1.y, cv1.y);
                    ffma2(acc[12], wv1.x, cv2.x); ffma2(acc[13], wv1.y, cv2.y);
                    ffma2(acc[14], wv1.x, cv3.x); ffma2(acc[15], wv1.y, cv3.y);
                    ffma2(acc[16], wv2.x, cv0.x); ffma2(acc[17], wv2.y, cv0.y);
                    ffma2(acc[18], wv2.x, cv1.x); ffma2(acc[19], wv2.y, cv1.y);
                    ffma2(acc[20], wv2.x, cv2.x); ffma2(acc[21], wv2.y, cv2.y);
                    ffma2(acc[22], wv2.x, cv3.x); ffma2(acc[23], wv2.y, cv3.y);
                    ffma2(acc[24], wv3.x, cv0.x); ffma2(acc[25], wv3.y, cv0.y);
                    ffma2(acc[26], wv3.x, cv1.x); ffma2(acc[27], wv3.y, cv1.y);
                    ffma2(acc[28], wv3.x, cv2.x); ffma2(acc[29], wv3.y, cv2.y);
                    ffma2(acc[30], wv3.x, cv3.x); ffma2(acc[31], wv3.y, cv3.y);
                }
                __syncthreads();
            }

            // ---- write per-ksplit partial sums (disjoint slabs, no sync) ----
            {
                float* slab = gs4 + ksplit * (64 * 33);
                #pragma unroll
                for (int j = 0; j < 4; j++)
                    #pragma unroll
                    for (int bt = 0; bt < 4; bt++) {
                        F2 u0, u1;
                        u0.u = acc[j * 8 + bt * 2 + 0];
                        u1.u = acc[j * 8 + bt * 2 + 1];
                        slab[(rbase + j) * 33 + blane * 4 + bt] =
                            u0.f.x + u0.f.y + u1.f.x + u1.f.y;
                    }
            }
            __syncthreads();

            // ---- pointwise, 1 item/thread ----
            float gsum[4];
            #pragma unroll
            for (int g = 0; g < 4; ++g) {
                const int row = g * 16 + nj;
                float v = gs4[row * 33 + pb];
                #pragma unroll
                for (int ks = 1; ks < 4; ++ks)
                    v += gs4[ks * (64 * 33) + row * 33 + pb];
                gsum[g] = v + br[g];
            }
            float fg = 1.f / (1.f + expf(-gsum[0]));
            float ig = 1.f / (1.f + expf(-gsum[1]));
            float og = 1.f / (1.f + expf(-gsum[3]));
            float c  = fg * cst + ig * tanhf(gsum[2]);
            cst = c;
            float h  = og * tanhf(c);

            const int wp = gsel ? ((s + 1) & 1) : (s & 1);   // write parity
            const int n  = gcta * 16 + nj;
            g_h[(gsel * 2 + wp) * 32768 + pb * HDIM + n] = h;
            if (gsel == 1)
                out[(size_t)pb * 524288 + (size_t)t * 1024 + n] = h;
            if (t == TSTEPS - 1) {
                out[16777216 + gsel * 32768 + pb * 1024 + n] = h;   // h_n
                out[16842752 + gsel * 32768 + pb * 1024 + n] = c;   // c_n
            }
        }

        grid_bar();
    }
}

extern "C" void kernel_launch(void* const* d_in, const int* in_sizes, int n_in,
                              void* d_out, int out_size)
{
    (void)in_sizes; (void)n_in; (void)out_size;
    const float* x  = (const float*)d_in[0];
    const float* W0 = (const float*)d_in[1];
    const float* b0 = (const float*)d_in[2];
    const float* W1 = (const float*)d_in[3];
    const float* b1 = (const float*)d_in[4];

    lstm_rearrange<<<4096, 256>>>(W0, W1);

    cudaFuncSetAttribute(lstm_persist,
                         cudaFuncAttributeMaxDynamicSharedMemorySize, SMEM_BYTES);
    lstm_persist<<<NCTA, NTHR, SMEM_BYTES>>>(x, b0, b1, (float*)d_out);
}

// round 8
// speedup vs baseline: 1.0002x; 1.0002x over previous
#include <cuda_runtime.h>
#include <cstdint>
#include <cstddef>

// ---------------------------------------------------------------------------
// 2-layer LSTM, B=32, T=512, I=H=1024, fp32 — wavefront-pipelined layers.
//
// CTAs 0..63   = group A: layer 0 at time t=s      (active s < 512)
// CTAs 64..127 = group B: layer 1 at time t=s-1    (active s >= 1)
// 513 wavefront steps, one grid barrier each. Per step each CTA does
// 64 gate-rows x 32 batches x k=2048:
//   - 16 k-stages of 128, cp.async 4-deep pipeline, ONE __syncthreads/stage
//   - 16 warps (512 thr): 4-way k-split x 4 row-blocks; thread tile
//     4 rows x 4 batches -> 32 FFMA2 per 8 LDS.128, conflict-free swizzles
//   - weights pre-rearranged once into per-(cta,stage) contiguous swizzled
//     blocks; c-state in registers for all 512 steps
// ---------------------------------------------------------------------------

#define NCTA   128
#define NTHR   512
#define TSTEPS 512
#define HDIM   1024

#define OFF_W   0u         // 4 x 32KB weight stage buffers
#define OFF_C   131072u    // 4 x 16KB comb stage buffers
#define OFF_GS  196608u    // gs4[4][64][33] partial gate sums
#define SMEM_BYTES (196608 + 4 * 64 * 33 * 4)   // 230400

// rearranged weights: [l][cta64][stage16][2048 float4] (row/kq swizzled)
__device__ __align__(16) float g_Wre[2u * 64u * 16u * 2048u * 4u];
// h ping-pong: [layer][pp][b*1024+n]
__device__ __align__(16) float g_h[2 * 2 * 32 * HDIM];
__device__ unsigned g_bar_count;
__device__ volatile unsigned g_bar_gen;

union F2 { unsigned long long u; float2 f; };

__device__ __forceinline__ void ffma2(unsigned long long& acc,
                                      unsigned long long a,
                                      unsigned long long b) {
    asm volatile("fma.rn.f32x2 %0, %1, %2, %0;" : "+l"(acc) : "l"(a), "l"(b));
}
__device__ __forceinline__ void cpa16(uint32_t dst, const void* src) {
    asm volatile("cp.async.cg.shared.global [%0], [%1], 16;" :: "r"(dst), "l"(src));
}
__device__ __forceinline__ void cp_commit() {
    asm volatile("cp.async.commit_group;");
}
template<int N> __device__ __forceinline__ void cp_wait() {
    asm volatile("cp.async.wait_group %0;" :: "n"(N));
}

__device__ __forceinline__ void grid_bar() {
    __syncthreads();
    if (threadIdx.x == 0) {
        __threadfence();
        unsigned gen = g_bar_gen;
        if (atomicAdd(&g_bar_count, 1u) == NCTA - 1) {
            g_bar_count = 0;
            __threadfence();
            g_bar_gen = gen + 1;
        } else {
            while (g_bar_gen == gen) { __nanosleep(32); }
        }
        __threadfence();
    }
    __syncthreads();
}

// stage weights: contiguous pre-swizzled 32KB block -> smem buffer
__device__ __forceinline__ void fetch_W(uint32_t sb, uint32_t dstoff,
                                        int l, int gcta, int s, int tid) {
    const float4* src = ((const float4*)g_Wre) +
                        (((size_t)l * 64 + gcta) * 16 + s) * 2048;
    uint32_t d = sb + OFF_W + dstoff;
    #pragma unroll
    for (int i = 0; i < 4; i++) {
        int m = tid + i * 512;
        cpa16(d + m * 16, src + m);
    }
}

// stage activations: 32 b x 128 k, swizzled slot c holds kq = c ^ (b>>2)
__device__ __forceinline__ void fetch_C(uint32_t sb, uint32_t dstoff,
                                        const float* base, size_t stride,
                                        int tid) {
    uint32_t d = sb + OFF_C + dstoff;
    #pragma unroll
    for (int i = 0; i < 2; i++) {
        int m = tid + i * 512;
        int b = m >> 5, c = m & 31;
        cpa16(d + m * 16,
              base + (size_t)b * stride + ((c ^ (b >> 2)) << 2));
    }
}

// one-time weight rearrangement
extern "C" __global__ void lstm_rearrange(const float* __restrict__ W0,
                                          const float* __restrict__ W1) {
    unsigned gid = blockIdx.x * 256u + threadIdx.x;
    #pragma unroll
    for (int i = 0; i < 4; i++) {
        unsigned m   = gid + (unsigned)i * 1048576u;
        unsigned c   = m & 31u;
        unsigned r   = (m >> 5) & 63u;
        unsigned s   = (m >> 11) & 15u;
        unsigned cta = (m >> 15) & 63u;
        unsigned l   = m >> 21;
        unsigned sw  = ((r >> 2) & 3u) * 2u;
        unsigned gr  = (r >> 4) * 1024u + cta * 16u + (r & 15u);
        const float* W = l ? W1 : W0;
        ((float4*)g_Wre)[m] =
            ((const float4*)W)[(size_t)gr * 512 + s * 32 + (c ^ sw)];
    }
}

extern "C" __global__ void __launch_bounds__(NTHR, 1)
lstm_persist(const float* __restrict__ x,
             const float* __restrict__ b0,
             const float* __restrict__ b1,
             float* __restrict__ out)
{
    extern __shared__ char sm[];
    const uint32_t sb = (uint32_t)__cvta_generic_to_shared(sm);
    float* gs4 = (float*)(sm + OFF_GS);      // [4][64][33]

    const int tid    = threadIdx.x;
    const int cta    = blockIdx.x;
    const int gsel   = cta >> 6;        // 0 = layer0 (A), 1 = layer1 (B)
    const int gcta   = cta & 63;
    const int w      = tid >> 5;        // 0..15
    const int lane   = tid & 31;
    const int ksplit = w >> 2;          // 0..3: kq-quarter within stage
    const int rblk   = w & 3;           // 4 row-blocks of 16 rows
    const int rlane  = lane >> 3;       // 0..3
    const int blane  = lane & 7;        // 0..7
    const int rbase  = rblk * 16 + rlane * 4;  // first of thread's 4 rows
    const int wsw    = rlane * 2;       // W kq swizzle for this thread

    // pointwise: 1 item per thread: (neuron nj, batch pb)
    const int nj = tid & 15, pb = tid >> 4;

    // zero h state
    {
        int base = cta * 1024 + tid;
        #pragma unroll
        for (int k = 0; k < 2; k++) g_h[base + k * 512] = 0.f;
    }

    const float* bias = gsel ? b1 : b0;
    float br[4];
    #pragma unroll
    for (int g = 0; g < 4; ++g)
        br[g] = bias[g * HDIM + gcta * 16 + nj];
    float cst = 0.f;

    grid_bar();

    #pragma unroll 1
    for (int s = 0; s <= TSTEPS; ++s) {
        const bool active = gsel ? (s >= 1) : (s < TSTEPS);
        const int  t      = gsel ? (s - 1) : s;          // my time index
        const int  pprev  = (s + 1) & 1;                 // h0(s-1) parity

        if (active) {
            // ---- stage source resolver ----
            auto src_of = [&](int st, const float*& base, size_t& stride) {
                if (gsel == 0) {
                    if (st < 8) { base = x + (size_t)t * 1024 + st * 128; stride = 524288; }
                    else        { base = g_h + pprev * 32768 + (st - 8) * 128; stride = 1024; }
                } else {
                    if (st < 8) { base = g_h + pprev * 32768 + st * 128; stride = 1024; }
                    else        { base = g_h + (2 + (s & 1)) * 32768 + (st - 8) * 128; stride = 1024; }
                }
            };

            // ---- bootstrap pipeline: stages 0,1 ----
            {
                const float* cb; size_t cs;
                fetch_W(sb, 0u, gsel, gcta, 0, tid);
                src_of(0, cb, cs); fetch_C(sb, 0u, cb, cs, tid);
                cp_commit();
                fetch_W(sb, 32768u, gsel, gcta, 1, tid);
                src_of(1, cb, cs); fetch_C(sb, 16384u, cb, cs, tid);
                cp_commit();
            }

            unsigned long long acc[32];
            #pragma unroll
            for (int i = 0; i < 32; i++) acc[i] = 0ull;

            #pragma unroll 1
            for (int st = 0; st < 16; ++st) {
                if (st + 2 < 16) {
                    const int nf = st + 2;
                    fetch_W(sb, (uint32_t)((nf & 3) << 15), gsel, gcta, nf, tid);
                    const float* cb; size_t cs;
                    src_of(nf, cb, cs);
                    fetch_C(sb, (uint32_t)((nf & 3) << 14), cb, cs, tid);
                }
                cp_commit();
                cp_wait<2>();
                __syncthreads();

                const char* Wp = sm + ((st & 3) << 15) + rbase * 512;
                const char* Cp = sm + OFF_C + ((st & 3) << 14) + blane * 2048;
                const int kq0 = ksplit * 8;
                #pragma unroll 4
                for (int kq = kq0; kq < kq0 + 8; ++kq) {
                    const int wo = (kq ^ wsw)   << 4;
                    const int co = (kq ^ blane) << 4;
                    ulonglong2 wv0 = *(const ulonglong2*)(Wp + wo);
                    ulonglong2 wv1 = *(const ulonglong2*)(Wp + wo + 512);
                    ulonglong2 wv2 = *(const ulonglong2*)(Wp + wo + 1024);
                    ulonglong2 wv3 = *(const ulonglong2*)(Wp + wo + 1536);
                    ulonglong2 cv0 = *(const ulonglong2*)(Cp + co);
                    ulonglong2 cv1 = *(const ulonglong2*)(Cp + co + 512);
                    ulonglong2 cv2 = *(const ulonglong2*)(Cp + co + 1024);
                    ulonglong2 cv3 = *(const ulonglong2*)(Cp + co + 1536);
                    ffma2(acc[0],  wv0.x, cv0.x); ffma2(acc[1],  wv0.y, cv0.y);
                    ffma2(acc[2],  wv0.x, cv1.x); ffma2(acc[3],  wv0.y, cv1.y);
                    ffma2(acc[4],  wv0.x, cv2.x); ffma2(acc[5],  wv0.y, cv2.y);
                    ffma2(acc[6],  wv0.x, cv3.x); ffma2(acc[7],  wv0.y, cv3.y);
                    ffma2(acc[8],  wv1.x, cv0.x); ffma2(acc[9],  wv1.y, cv0.y);
                    ffma2(acc[10], wv1.x, cv1.x); ffma2(acc[11], wv1.y, cv1.y);
                    ffma2(acc[12], wv1.x, cv2.x); ffma2(acc[13], wv1.y, cv2.y);
                    ffma2(acc[14], wv1.x, cv3.x); ffma2(acc[15], wv1.y, cv3.y);
                    ffma2(acc[16], wv2.x, cv0.x); ffma2(acc[17], wv2.y, cv0.y);
                    ffma2(acc[18], wv2.x, cv1.x); ffma2(acc[19], wv2.y, cv1.y);
                    ffma2(acc[20], wv2.x, cv2.x); ffma2(acc[21], wv2.y, cv2.y);
                    ffma2(acc[22], wv2.x, cv3.x); ffma2(acc[23], wv2.y, cv3.y);
                    ffma2(acc[24], wv3.x, cv0.x); ffma2(acc[25], wv3.y, cv0.y);
                    ffma2(acc[26], wv3.x, cv1.x); ffma2(acc[27], wv3.y, cv1.y);
                    ffma2(acc[28], wv3.x, cv2.x); ffma2(acc[29], wv3.y, cv2.y);
                    ffma2(acc[30], wv3.x, cv3.x); ffma2(acc[31], wv3.y, cv3.y);
                }
                __syncthreads();
            }

            // ---- write per-ksplit partial sums (disjoint slabs, no sync) ----
            {
                float* slab = gs4 + ksplit * (64 * 33);
                #pragma unroll
                for (int j = 0; j < 4; j++)
                    #pragma unroll
                    for (int bt = 0; bt < 4; bt++) {
                        F2 u0, u1;
                        u0.u = acc[j * 8 + bt * 2 + 0];
                        u1.u = acc[j * 8 + bt * 2 + 1];
                        slab[(rbase + j) * 33 + blane * 4 + bt] =
                            u0.f.x + u0.f.y + u1.f.x + u1.f.y;
                    }
            }
            __syncthreads();

            // ---- pointwise, 1 item/thread ----
            float gsum[4];
            #pragma unroll
            for (int g = 0; g < 4; ++g) {
                const int row = g * 16 + nj;
                float v = gs4[row * 33 + pb];
                #pragma unroll
                for (int ks = 1; ks < 4; ++ks)
                    v += gs4[ks * (64 * 33) + row * 33 + pb];
                gsum[g] = v + br[g];
            }
            float fg = 1.f / (1.f + expf(-gsum[0]));
            float ig = 1.f / (1.f + expf(-gsum[1]));
            float og = 1.f / (1.f + expf(-gsum[3]));
            float c  = fg * cst + ig * tanhf(gsum[2]);
            cst = c;
            float h  = og * tanhf(c);

            const int wp = gsel ? ((s + 1) & 1) : (s & 1);   // write parity
            const int n  = gcta * 16 + nj;
            g_h[(gsel * 2 + wp) * 32768 + pb * HDIM + n] = h;
            if (gsel == 1)
                out[(size_t)pb * 524288 + (size_t)t * 1024 + n] = h;
            if (t == TSTEPS - 1) {
                out[16777216 + gsel * 32768 + pb * 1024 + n] = h;   // h_n
                out[16842752 + gsel * 32768 + pb * 1024 + n] = c;   // c_n
            }
        }

        grid_bar();
    }
}

extern "C" void kernel_launch(void* const* d_in, const int* in_sizes, int n_in,
                              void* d_out, int out_size)
{
    (void)in_sizes; (void)n_in; (void)out_size;
    const float* x  = (const float*)d_in[0];
    const float* W0 = (const float*)d_in[1];
    const float* b0 = (const float*)d_in[2];
    const float* W1 = (const float*)d_in[3];
    const float* b1 = (const float*)d_in[4];

    lstm_rearrange<<<4096, 256>>>(W0, W1);

    cudaFuncSetAttribute(lstm_persist,
                         cudaFuncAttributeMaxDynamicSharedMemorySize, SMEM_BYTES);
    lstm_persist<<<NCTA, NTHR, SMEM_BYTES>>>(x, b0, b1, (float*)d_out);
}

// round 10
// speedup vs baseline: 2.4259x; 2.4253x over previous
#include <cuda_runtime.h>
#include <cuda_bf16.h>
#include <cstdint>
#include <cstddef>

// ---------------------------------------------------------------------------
// 2-layer LSTM, B=32, T=512, I=H=1024, fp32 I/O.
// Tensor-core path via baseline ISA: ldmatrix + mma.sync.m16n8k16.bf16.f32
// (compiles for compute_103 — no tcgen05, which the harness toolchain rejects).
// Markidis split: W=Whi+Wlo, C=Chi+Clo; D = WhiChi + WhiClo + WloChi (fp32 acc).
//
// 128 CTAs x 512 thr, wavefront: CTAs 0..63 layer0 @ t=s, 64..127 layer1 @ s-1,
// 513 steps, grid barrier each. Per CTA/step: D[64 rows x 32 batch], K=2048 as
// 16 stages x 128k, cp.async double-buffered; 16 warps = 4 row-groups(16 rows)
// x 4 k-splits(32k); per k16: 6 ldmatrix.x4 + 12 mma. Weights/x pre-split into
// per-(cta,stage) swizzled bf16 images; h written back as bf16 hi/lo images.
// ---------------------------------------------------------------------------

#define NCTA 128
#define NTHR 512
#define TSTEPS 512
#define BUFSZ 49152u
#define SMEM_BYTES (2 * 49152)

__device__ __align__(16) unsigned char g_Whi[2u*64u*16u*16384u];  // 32 MB
__device__ __align__(16) unsigned char g_Wlo[2u*64u*16u*16384u];  // 32 MB
__device__ __align__(16) unsigned char g_xhi[512u*8u*8192u];      // 32 MB
__device__ __align__(16) unsigned char g_xlo[512u*8u*8192u];      // 32 MB
__device__ __align__(16) unsigned char g_h0hi[2*8*8192];
__device__ __align__(16) unsigned char g_h0lo[2*8*8192];
__device__ __align__(16) unsigned char g_h1hi[2*8*8192];
__device__ __align__(16) unsigned char g_h1lo[2*8*8192];
__device__ unsigned g_bar_count;
__device__ volatile unsigned g_bar_gen;

__device__ __forceinline__ void cpa16(uint32_t d, const void* s) {
    asm volatile("cp.async.cg.shared.global [%0], [%1], 16;" :: "r"(d), "l"(s));
}
__device__ __forceinline__ void cp_commit() { asm volatile("cp.async.commit_group;"); }
template<int N> __device__ __forceinline__ void cp_wait() {
    asm volatile("cp.async.wait_group %0;" :: "n"(N));
}
#define LDSM4(R, A) \
    asm volatile("ldmatrix.sync.aligned.m8n8.x4.shared.b16 {%0,%1,%2,%3}, [%4];" \
        : "=r"((R)[0]), "=r"((R)[1]), "=r"((R)[2]), "=r"((R)[3]) : "r"(A))
#define MMA(D, A, B0, B1) \
    asm volatile("mma.sync.aligned.m16n8k16.row.col.f32.bf16.bf16.f32 " \
        "{%0,%1,%2,%3}, {%4,%5,%6,%7}, {%8,%9}, {%0,%1,%2,%3};" \
        : "+f"((D)[0]), "+f"((D)[1]), "+f"((D)[2]), "+f"((D)[3]) \
        : "r"((A)[0]), "r"((A)[1]), "r"((A)[2]), "r"((A)[3]), "r"(B0), "r"(B1))

__device__ __forceinline__ void grid_bar() {
    __syncthreads();
    if (threadIdx.x == 0) {
        __threadfence();
        unsigned gen = g_bar_gen;
        if (atomicAdd(&g_bar_count, 1u) == NCTA - 1) {
            g_bar_count = 0; __threadfence(); g_bar_gen = gen + 1;
        } else { while (g_bar_gen == gen) { __nanosleep(32); } }
        __threadfence();
    }
    __syncthreads();
}

// split a float into bf16 hi + bf16 lo
__device__ __forceinline__ void split_bf16(float v, unsigned short* hi,
                                           unsigned short* lo) {
    __nv_bfloat16 h = __float2bfloat16_rn(v);
    __nv_bfloat16 l = __float2bfloat16_rn(v - __bfloat162float(h));
    *hi = __bfloat16_as_ushort(h);
    *lo = __bfloat16_as_ushort(l);
}

// ---- prep: per-(cta,stage) swizzled W images (64 rows x 128 k) ----
extern "C" __global__ void prep_w(const float* __restrict__ W0,
                                  const float* __restrict__ W1) {
    unsigned m = blockIdx.x * 512u + threadIdx.x;     // < 2^21
    unsigned p = m & 1023u, st = (m >> 10) & 15u;
    unsigned mblk = (m >> 14) & 63u, l = (m >> 20) & 1u;
    unsigned r = p >> 4, c16 = (p & 15u) ^ (r & 7u);
    const float* W = l ? W1 : W0;
    unsigned grow = (r >> 4) * 1024u + mblk * 16u + (r & 15u);
    const float* src = W + (size_t)grow * 2048 + st * 128 + c16 * 8;
    union { unsigned short us[8]; uint4 q; } hq, lq;
    #pragma unroll
    for (int e = 0; e < 8; ++e) split_bf16(src[e], &hq.us[e], &lq.us[e]);
    size_t base = ((size_t)(l * 64u + mblk) * 16u + st) * 16384u + p * 16u;
    *(uint4*)(g_Whi + base) = hq.q;
    *(uint4*)(g_Wlo + base) = lq.q;
}
// ---- prep: per-(t,stage) swizzled x images (32 b x 128 k) ----
extern "C" __global__ void prep_x(const float* __restrict__ x) {
    unsigned m = blockIdx.x * 512u + threadIdx.x;     // < 2^21
    unsigned p = m & 511u, st = (m >> 9) & 7u, t = (m >> 12) & 511u;
    unsigned b = p >> 4, c16 = (p & 15u) ^ (b & 7u);
    const float* src = x + (size_t)b * 524288 + (size_t)t * 1024 + st * 128 + c16 * 8;
    union { unsigned short us[8]; uint4 q; } hq, lq;
    #pragma unroll
    for (int e = 0; e < 8; ++e) split_bf16(src[e], &hq.us[e], &lq.us[e]);
    size_t base = ((size_t)t * 8u + st) * 8192u + p * 16u;
    *(uint4*)(g_xhi + base) = hq.q;
    *(uint4*)(g_xlo + base) = lq.q;
}
extern "C" __global__ void prep_zero() {
    unsigned i = blockIdx.x * 512u + threadIdx.x;     // < 32768
    ((unsigned*)g_h0hi)[i] = 0u; ((unsigned*)g_h0lo)[i] = 0u;
    ((unsigned*)g_h1hi)[i] = 0u; ((unsigned*)g_h1lo)[i] = 0u;
}

// ---- main persistent kernel ----
extern "C" __global__ void __launch_bounds__(NTHR, 1)
lstm_mma(const float* __restrict__ b0, const float* __restrict__ b1,
         float* __restrict__ out)
{
    extern __shared__ char sm[];
    const uint32_t sb = (uint32_t)__cvta_generic_to_shared(sm);
    float* gs = (float*)sm;                       // overlays buffer 0

    const int tid = threadIdx.x, cta = blockIdx.x;
    const int l = cta >> 6, mblk = cta & 63;
    const int wv = tid >> 5, lane = tid & 31;
    const int ksplit = wv >> 2, rg = wv & 3;
    const uint32_t lx7 = lane & 7;
    const uint32_t Aoff  = (uint32_t)(rg * 16 + (lane & 15)) * 256u;
    const uint32_t Boff0 = (uint32_t)((lane & 7) + ((lane >> 4) << 3)) * 256u;
    const uint32_t Boff1 = Boff0 + 16u * 256u;
    const uint32_t acb = (lane >> 4) & 1, bcb = (lane >> 3) & 1;

    // pointwise item
    const int pj = tid & 15, pb = tid >> 4;       // neuron-in-cta, batch
    const int n = mblk * 16 + pj;

    const float* bias = l ? b1 : b0;
    float br[4];
    #pragma unroll
    for (int g = 0; g < 4; ++g) br[g] = bias[g * 1024 + n];
    float cst = 0.f;
    const size_t wbase = (size_t)cta * 262144u;   // 16 stages * 16KB

    grid_bar();                                    // preps done chip-wide

    #pragma unroll 1
    for (int s = 0; s <= TSTEPS; ++s) {
        const bool active = l ? (s >= 1) : (s < TSTEPS);
        if (active) {
            const int t = l ? (s - 1) : s;
            const int rp = (s + 1) & 1, wp = s & 1;

            auto fetch = [&](int st) {
                uint32_t buf = sb + (uint32_t)(st & 1) * BUFSZ;
                const unsigned char* wh = g_Whi + wbase + (size_t)st * 16384u;
                const unsigned char* wl = g_Wlo + wbase + (size_t)st * 16384u;
                cpa16(buf + tid * 16,         wh + tid * 16);
                cpa16(buf + 8192 + tid * 16,  wh + 8192 + tid * 16);
                cpa16(buf + 16384 + tid * 16, wl + tid * 16);
                cpa16(buf + 24576 + tid * 16, wl + 8192 + tid * 16);
                const unsigned char *ch, *cl;
                if (l == 0) {
                    if (st < 8) { ch = g_xhi + ((size_t)t * 8 + st) * 8192u;
                                  cl = g_xlo + ((size_t)t * 8 + st) * 8192u; }
                    else        { ch = g_h0hi + (rp * 8 + st - 8) * 8192;
                                  cl = g_h0lo + (rp * 8 + st - 8) * 8192; }
                } else {
                    if (st < 8) { ch = g_h0hi + (rp * 8 + st) * 8192;
                                  cl = g_h0lo + (rp * 8 + st) * 8192; }
                    else        { ch = g_h1hi + (rp * 8 + st - 8) * 8192;
                                  cl = g_h1lo + (rp * 8 + st - 8) * 8192; }
                }
                cpa16(buf + 32768 + tid * 16, ch + tid * 16);
                cpa16(buf + 40960 + tid * 16, cl + tid * 16);
                cp_commit();
            };

            float d[4][4];
            #pragma unroll
            for (int j = 0; j < 4; ++j)
                #pragma unroll
                for (int e = 0; e < 4; ++e) d[j][e] = 0.f;

            fetch(0); fetch(1);
            #pragma unroll 1
            for (int st = 0; st < 16; ++st) {
                if (st == 15) cp_wait<0>(); else cp_wait<1>();
                __syncthreads();
                const uint32_t buf = sb + (uint32_t)(st & 1) * BUFSZ;
                #pragma unroll
                for (int kk = 0; kk < 2; ++kk) {
                    const uint32_t c0k = (uint32_t)(ksplit * 4 + kk * 2);
                    const uint32_t ac = ((c0k + acb) ^ lx7) << 4;
                    const uint32_t bc = ((c0k + bcb) ^ lx7) << 4;
                    uint32_t AH[4], AL[4], BH0[4], BH1[4], BL0[4], BL1[4];
                    LDSM4(AH,  buf + Aoff + ac);
                    LDSM4(AL,  buf + 16384 + Aoff + ac);
                    LDSM4(BH0, buf + 32768 + Boff0 + bc);
                    LDSM4(BH1, buf + 32768 + Boff1 + bc);
                    LDSM4(BL0, buf + 40960 + Boff0 + bc);
                    LDSM4(BL1, buf + 40960 + Boff1 + bc);
                    #pragma unroll
                    for (int j = 0; j < 4; ++j) {
                        uint32_t* bh = (j & 2) ? BH1 : BH0;
                        uint32_t* bl = (j & 2) ? BL1 : BL0;
                        const int o = (j & 1) * 2;
                        MMA(d[j], AH, bh[o], bh[o + 1]);
                        MMA(d[j], AH, bl[o], bl[o + 1]);
                        MMA(d[j], AL, bh[o], bh[o + 1]);
                    }
                }
                __syncthreads();
                if (st + 2 < 16) fetch(st + 2);
            }

            // ---- partial sums -> gs[4][64][34] (overlays buffer 0) ----
            {
                float* slab = gs + ksplit * 2176;
                const int r1 = rg * 16 + (lane >> 2);
                #pragma unroll
                for (int j = 0; j < 4; ++j) {
                    const int c = j * 8 + 2 * (lane & 3);
                    *(float2*)&slab[r1 * 34 + c] = make_float2(d[j][0], d[j][1]);
                    *(float2*)&slab[(r1 + 8) * 34 + c] = make_float2(d[j][2], d[j][3]);
                }
            }
            __syncthreads();

            // ---- pointwise: thread owns (neuron pj, batch pb) ----
            float gsum[4];
            #pragma unroll
            for (int g = 0; g < 4; ++g) {
                const int row = g * 16 + pj;
                float v = gs[row * 34 + pb];
                #pragma unroll
                for (int ks = 1; ks < 4; ++ks)
                    v += gs[ks * 2176 + row * 34 + pb];
                gsum[g] = v + br[g];
            }
            float fg = 1.f / (1.f + expf(-gsum[0]));
            float ig = 1.f / (1.f + expf(-gsum[1]));
            float og = 1.f / (1.f + expf(-gsum[3]));
            float c = fg * cst + ig * tanhf(gsum[2]);
            cst = c;
            float h = og * tanhf(c);

            // write h as bf16 hi/lo into swizzled images
            unsigned short hh, hl;
            split_bf16(h, &hh, &hl);
            const int st8 = n >> 7, c16 = (n >> 3) & 15, i8 = n & 7;
            size_t off = (size_t)(wp * 8 + st8) * 8192u + pb * 256u
                       + (unsigned)((c16 ^ (pb & 7)) * 16) + i8 * 2u;
            if (l == 0) {
                *(unsigned short*)(g_h0hi + off) = hh;
                *(unsigned short*)(g_h0lo + off) = hl;
            } else {
                *(unsigned short*)(g_h1hi + off) = hh;
                *(unsigned short*)(g_h1lo + off) = hl;
                out[(size_t)pb * 524288 + (size_t)t * 1024 + n] = h;
            }
            if (t == TSTEPS - 1) {
                out[16777216 + l * 32768 + pb * 1024 + n] = h;   // h_n
                out[16842752 + l * 32768 + pb * 1024 + n] = c;   // c_n
            }
        }
        grid_bar();
    }
}

extern "C" void kernel_launch(void* const* d_in, const int* in_sizes, int n_in,
                              void* d_out, int out_size)
{
    (void)in_sizes; (void)n_in; (void)out_size;
    const float* x  = (const float*)d_in[0];
    const float* W0 = (const float*)d_in[1];
    const float* b0 = (const float*)d_in[2];
    const float* W1 = (const float*)d_in[3];
    const float* b1 = (const float*)d_in[4];

    prep_w<<<4096, 512>>>(W0, W1);
    prep_x<<<4096, 512>>>(x);
    prep_zero<<<64, 512>>>();

    cudaFuncSetAttribute(lstm_mma,
                         cudaFuncAttributeMaxDynamicSharedMemorySize, SMEM_BYTES);
    lstm_mma<<<NCTA, NTHR, SMEM_BYTES>>>(b0, b1, (float*)d_out);
}

// round 11
// speedup vs baseline: 2.5214x; 1.0394x over previous
#include <cuda_runtime.h>
#include <cuda_bf16.h>
#include <cstdint>
#include <cstddef>

// ---------------------------------------------------------------------------
// 2-layer LSTM, B=32, T=512, I=H=1024, fp32 I/O.
// ldmatrix + mma.sync.m16n8k16.bf16.f32 (compute_103-safe), Markidis split:
// D = WhiChi + WhiClo + WloChi, fp32 accum.
// 128 CTAs x 512 thr wavefront (layer0 @ s, layer1 @ s-1), 513 steps.
// Per CTA/step: D[64 rows x 32 batch], K=2048 = 8 stages x 256k,
// 2 x 96KB smem buffers, 1 __syncthreads + 1 cp.wait per stage.
// 16 warps = 2 row-groups(32 rows) x 8 k-splits(32k): per k16 8 ldmatrix.x4
// + 24 mma (B fragments shared by only 2 warps -> crossbar < tensor).
// Weight stage 0 prefetched pre-barrier (weights step-invariant).
// ---------------------------------------------------------------------------

#define NCTA 128
#define NTHR 512
#define TSTEPS 512
#define BUFSZ 98304u
#define SMEM_BYTES (2 * 98304)

__device__ __align__(16) unsigned char g_Whi[2u*64u*16u*16384u];  // 32 MB
__device__ __align__(16) unsigned char g_Wlo[2u*64u*16u*16384u];  // 32 MB
__device__ __align__(16) unsigned char g_xhi[512u*8u*8192u];      // 32 MB
__device__ __align__(16) unsigned char g_xlo[512u*8u*8192u];      // 32 MB
__device__ __align__(16) unsigned char g_h0hi[2*8*8192];
__device__ __align__(16) unsigned char g_h0lo[2*8*8192];
__device__ __align__(16) unsigned char g_h1hi[2*8*8192];
__device__ __align__(16) unsigned char g_h1lo[2*8*8192];
__device__ unsigned g_bar_count;
__device__ volatile unsigned g_bar_gen;

__device__ __forceinline__ void cpa16(uint32_t d, const void* s) {
    asm volatile("cp.async.cg.shared.global [%0], [%1], 16;" :: "r"(d), "l"(s));
}
__device__ __forceinline__ void cp_commit() { asm volatile("cp.async.commit_group;"); }
template<int N> __device__ __forceinline__ void cp_wait() {
    asm volatile("cp.async.wait_group %0;" :: "n"(N));
}
#define LDSM4(R, A) \
    asm volatile("ldmatrix.sync.aligned.m8n8.x4.shared.b16 {%0,%1,%2,%3}, [%4];" \
        : "=r"((R)[0]), "=r"((R)[1]), "=r"((R)[2]), "=r"((R)[3]) : "r"(A))
#define MMA(D, A, B0, B1) \
    asm volatile("mma.sync.aligned.m16n8k16.row.col.f32.bf16.bf16.f32 " \
        "{%0,%1,%2,%3}, {%4,%5,%6,%7}, {%8,%9}, {%0,%1,%2,%3};" \
        : "+f"((D)[0]), "+f"((D)[1]), "+f"((D)[2]), "+f"((D)[3]) \
        : "r"((A)[0]), "r"((A)[1]), "r"((A)[2]), "r"((A)[3]), "r"(B0), "r"(B1))

__device__ __forceinline__ void grid_bar() {
    __syncthreads();
    if (threadIdx.x == 0) {
        __threadfence();
        unsigned gen = g_bar_gen;
        if (atomicAdd(&g_bar_count, 1u) == NCTA - 1) {
            g_bar_count = 0; __threadfence(); g_bar_gen = gen + 1;
        } else { while (g_bar_gen == gen) { __nanosleep(32); } }
        __threadfence();
    }
    __syncthreads();
}

__device__ __forceinline__ void split_bf16(float v, unsigned short* hi,
                                           unsigned short* lo) {
    __nv_bfloat16 h = __float2bfloat16_rn(v);
    __nv_bfloat16 l = __float2bfloat16_rn(v - __bfloat162float(h));
    *hi = __bfloat16_as_ushort(h);
    *lo = __bfloat16_as_ushort(l);
}

// ---- prep: per-(cta,stage) swizzled W images (64 rows x 128 k, 16KB) ----
extern "C" __global__ void prep_w(const float* __restrict__ W0,
                                  const float* __restrict__ W1) {
    unsigned m = blockIdx.x * 512u + threadIdx.x;     // < 2^21
    unsigned p = m & 1023u, st = (m >> 10) & 15u;
    unsigned mblk = (m >> 14) & 63u, l = (m >> 20) & 1u;
    unsigned r = p >> 4, c16 = (p & 15u) ^ (r & 7u);
    const float* W = l ? W1 : W0;
    unsigned grow = (r >> 4) * 1024u + mblk * 16u + (r & 15u);
    const float* src = W + (size_t)grow * 2048 + st * 128 + c16 * 8;
    union { unsigned short us[8]; uint4 q; } hq, lq;
    #pragma unroll
    for (int e = 0; e < 8; ++e) split_bf16(src[e], &hq.us[e], &lq.us[e]);
    size_t base = ((size_t)(l * 64u + mblk) * 16u + st) * 16384u + p * 16u;
    *(uint4*)(g_Whi + base) = hq.q;
    *(uint4*)(g_Wlo + base) = lq.q;
}
// ---- prep: per-(t,stage) swizzled x images (32 b x 128 k, 8KB) ----
extern "C" __global__ void prep_x(const float* __restrict__ x) {
    unsigned m = blockIdx.x * 512u + threadIdx.x;     // < 2^21
    unsigned p = m & 511u, st = (m >> 9) & 7u, t = (m >> 12) & 511u;
    unsigned b = p >> 4, c16 = (p & 15u) ^ (b & 7u);
    const float* src = x + (size_t)b * 524288 + (size_t)t * 1024 + st * 128 + c16 * 8;
    union { unsigned short us[8]; uint4 q; } hq, lq;
    #pragma unroll
    for (int e = 0; e < 8; ++e) split_bf16(src[e], &hq.us[e], &lq.us[e]);
    size_t base = ((size_t)t * 8u + st) * 8192u + p * 16u;
    *(uint4*)(g_xhi + base) = hq.q;
    *(uint4*)(g_xlo + base) = lq.q;
}
extern "C" __global__ void prep_zero() {
    unsigned i = blockIdx.x * 512u + threadIdx.x;     // < 32768
    ((unsigned*)g_h0hi)[i] = 0u; ((unsigned*)g_h0lo)[i] = 0u;
    ((unsigned*)g_h1hi)[i] = 0u; ((unsigned*)g_h1lo)[i] = 0u;
}

// ---- main persistent kernel ----
extern "C" __global__ void __launch_bounds__(NTHR, 1)
lstm_mma(const float* __restrict__ b0, const float* __restrict__ b1,
         float* __restrict__ out)
{
    extern __shared__ char sm[];
    const uint32_t sb = (uint32_t)__cvta_generic_to_shared(sm);
    float* gs = (float*)(sm + BUFSZ);   // overlays buffer 1: [8][64][34] floats

    const int tid = threadIdx.x, cta = blockIdx.x;
    const int l = cta >> 6, mblk = cta & 63;
    const int wv = tid >> 5, lane = tid & 31;
    const int rg = wv & 1, ksplit = wv >> 1;        // 2 row-groups x 8 k-splits
    const uint32_t sub = (uint32_t)(ksplit >> 2);   // which 128k half of stage
    const uint32_t c0base = (uint32_t)((ksplit & 3) * 4);
    const uint32_t lx7 = lane & 7;
    const uint32_t Aoff = (uint32_t)(rg * 32 + (lane & 15)) * 256u;
    const uint32_t Boff = (uint32_t)((lane & 7) + ((lane >> 4) << 3)) * 256u;
    const uint32_t acb = (lane >> 4) & 1, bcb = (lane >> 3) & 1;

    // pointwise item
    const int pj = tid & 15, pb = tid >> 4;
    const int n = mblk * 16 + pj;

    const float* bias = l ? b1 : b0;
    float br[4];
    #pragma unroll
    for (int g = 0; g < 4; ++g) br[g] = bias[g * 1024 + n];
    float cst = 0.f;
    const size_t wbase = (size_t)cta * 262144u;     // 16 images * 16KB

    // fetch weights for 256k stage st into buffer st&1 (W region: 64KB)
    auto fetch_w = [&](int st) {
        uint32_t buf = sb + (uint32_t)(st & 1) * BUFSZ;
        const unsigned char* wh = g_Whi + wbase + (size_t)st * 32768u;
        const unsigned char* wl = g_Wlo + wbase + (size_t)st * 32768u;
        #pragma unroll
        for (int i = 0; i < 4; ++i) {
            cpa16(buf + i * 8192u + tid * 16, wh + i * 8192 + tid * 16);
            cpa16(buf + 32768u + i * 8192u + tid * 16, wl + i * 8192 + tid * 16);
        }
    };
    // fetch activations for stage st (C region: 32KB)
    auto fetch_c = [&](int st, int t, int rp) {
        uint32_t buf = sb + (uint32_t)(st & 1) * BUFSZ;
        const int kst = st * 2;
        const unsigned char *ch, *cl;
        if (l == 0) {
            if (st < 4) { ch = g_xhi + ((size_t)t * 8 + kst) * 8192u;
                          cl = g_xlo + ((size_t)t * 8 + kst) * 8192u; }
            else        { ch = g_h0hi + (rp * 8 + kst - 8) * 8192;
                          cl = g_h0lo + (rp * 8 + kst - 8) * 8192; }
        } else {
            if (st < 4) { ch = g_h0hi + (rp * 8 + kst) * 8192;
                          cl = g_h0lo + (rp * 8 + kst) * 8192; }
            else        { ch = g_h1hi + (rp * 8 + kst - 8) * 8192;
                          cl = g_h1lo + (rp * 8 + kst - 8) * 8192; }
        }
        #pragma unroll
        for (int i = 0; i < 2; ++i) {
            cpa16(buf + 65536u + i * 8192u + tid * 16, ch + i * 8192 + tid * 16);
            cpa16(buf + 81920u + i * 8192u + tid * 16, cl + i * 8192 + tid * 16);
        }
    };

    // stage-0 weights of first step prefetched before the initial barrier
    if (l == 0) { fetch_w(0); cp_commit(); }
    grid_bar();                                      // preps visible chip-wide

    #pragma unroll 1
    for (int s = 0; s <= TSTEPS; ++s) {
        const bool active = l ? (s >= 1) : (s < TSTEPS);
        if (active) {
            const int t = l ? (s - 1) : s;
            const int rp = (s + 1) & 1, wp = s & 1;

            fetch_c(0, t, rp); cp_commit();          // W0 already in flight

            float d[2][4][4];
            #pragma unroll
            for (int mt = 0; mt < 2; ++mt)
                #pragma unroll
                for (int j = 0; j < 4; ++j)
                    #pragma unroll
                    for (int e = 0; e < 4; ++e) d[mt][j][e] = 0.f;

            #pragma unroll 1
            for (int st = 0; st < 8; ++st) {
                cp_wait<0>();
                __syncthreads();                     // all copies visible; prev reads done
                if (st < 7) { fetch_w(st + 1); fetch_c(st + 1, t, rp); cp_commit(); }

                const uint32_t buf = sb + (uint32_t)(st & 1) * BUFSZ;
                const uint32_t wAhi = buf + sub * 16384u + Aoff;
                const uint32_t wAlo = wAhi + 32768u;
                const uint32_t cBhi = buf + 65536u + sub * 8192u + Boff;
                const uint32_t cBlo = cBhi + 16384u;
                #pragma unroll
                for (int kk = 0; kk < 2; ++kk) {
                    const uint32_t c0k = c0base + (uint32_t)kk * 2u;
                    const uint32_t ac = ((c0k + acb) ^ lx7) << 4;
                    const uint32_t bc = ((c0k + bcb) ^ lx7) << 4;
                    uint32_t AH0[4], AH1[4], AL0[4], AL1[4];
                    uint32_t BH0[4], BH1[4], BL0[4], BL1[4];
                    LDSM4(AH0, wAhi + ac);
                    LDSM4(AH1, wAhi + 4096u + ac);
                    LDSM4(AL0, wAlo + ac);
                    LDSM4(AL1, wAlo + 4096u + ac);
                    LDSM4(BH0, cBhi + bc);
                    LDSM4(BH1, cBhi + 4096u + bc);
                    LDSM4(BL0, cBlo + bc);
                    LDSM4(BL1, cBlo + 4096u + bc);
                    #pragma unroll
                    for (int mt = 0; mt < 2; ++mt) {
                        uint32_t* ah = mt ? AH1 : AH0;
                        uint32_t* al = mt ? AL1 : AL0;
                        #pragma unroll
                        for (int j = 0; j < 4; ++j) {
                            uint32_t* bh = (j & 2) ? BH1 : BH0;
                            uint32_t* bl = (j & 2) ? BL1 : BL0;
                            const int o = (j & 1) * 2;
                            MMA(d[mt][j], ah, bh[o], bh[o + 1]);
                            MMA(d[mt][j], ah, bl[o], bl[o + 1]);
                            MMA(d[mt][j], al, bh[o], bh[o + 1]);
                        }
                    }
                }
            }
            __syncthreads();                          // buffer-1 reads done -> gs safe

            // ---- partial sums -> gs[8][64][34] (overlays buffer 1) ----
            {
                float* slab = gs + ksplit * 2176;
                #pragma unroll
                for (int mt = 0; mt < 2; ++mt) {
                    const int r1 = rg * 32 + mt * 16 + (lane >> 2);
                    #pragma unroll
                    for (int j = 0; j < 4; ++j) {
                        const int c = j * 8 + 2 * (lane & 3);
                        *(float2*)&slab[r1 * 34 + c] =
                            make_float2(d[mt][j][0], d[mt][j][1]);
                        *(float2*)&slab[(r1 + 8) * 34 + c] =
                            make_float2(d[mt][j][2], d[mt][j][3]);
                    }
                }
            }
            __syncthreads();

            // ---- pointwise: thread owns (neuron pj, batch pb) ----
            float gsum[4];
            #pragma unroll
            for (int g = 0; g < 4; ++g) {
                const int row = g * 16 + pj;
                float v = 0.f;
                #pragma unroll
                for (int ks = 0; ks < 8; ++ks)
                    v += gs[ks * 2176 + row * 34 + pb];
                gsum[g] = v + br[g];
            }
            float fg = 1.f / (1.f + expf(-gsum[0]));
            float ig = 1.f / (1.f + expf(-gsum[1]));
            float og = 1.f / (1.f + expf(-gsum[3]));
            float c = fg * cst + ig * tanhf(gsum[2]);
            cst = c;
            float h = og * tanhf(c);

            unsigned short hh, hl;
            split_bf16(h, &hh, &hl);
            const int st8 = n >> 7, c16 = (n >> 3) & 15, i8 = n & 7;
            size_t off = (size_t)(wp * 8 + st8) * 8192u + pb * 256u
                       + (unsigned)((c16 ^ (pb & 7)) * 16) + i8 * 2u;
            if (l == 0) {
                *(unsigned short*)(g_h0hi + off) = hh;
                *(unsigned short*)(g_h0lo + off) = hl;
            } else {
                *(unsigned short*)(g_h1hi + off) = hh;
                *(unsigned short*)(g_h1lo + off) = hl;
                out[(size_t)pb * 524288 + (size_t)t * 1024 + n] = h;
            }
            if (t == TSTEPS - 1) {
                out[16777216 + l * 32768 + pb * 1024 + n] = h;   // h_n
                out[16842752 + l * 32768 + pb * 1024 + n] = c;   // c_n
            }
        }

        // prefetch next step's stage-0 weights before the barrier
        const bool nxt = l ? (s < TSTEPS) : (s + 1 < TSTEPS);
        if (nxt) { fetch_w(0); cp_commit(); }
        grid_bar();
    }
}

extern "C" void kernel_launch(void* const* d_in, const int* in_sizes, int n_in,
                              void* d_out, int out_size)
{
    (void)in_sizes; (void)n_in; (void)out_size;
    const float* x  = (const float*)d_in[0];
    const float* W0 = (const float*)d_in[1];
    const float* b0 = (const float*)d_in[2];
    const float* W1 = (const float*)d_in[3];
    const float* b1 = (const float*)d_in[4];

    prep_w<<<4096, 512>>>(W0, W1);
    prep_x<<<4096, 512>>>(x);
    prep_zero<<<64, 512>>>();

    cudaFuncSetAttribute(lstm_mma,
                         cudaFuncAttributeMaxDynamicSharedMemorySize, SMEM_BYTES);
    lstm_mma<<<NCTA, NTHR, SMEM_BYTES>>>(b0, b1, (float*)d_out);
}